// round 6
// baseline (speedup 1.0000x reference)
#include <cuda_runtime.h>

#define NROWS   32768
#define DCOLS   2048
#define C4TOT   (DCOLS / 4)            // 512 float4 columns
#define SLABC4  64                     // float4 cols per slab = 256 scalar cols = 32 MB
#define NSLABS  (C4TOT / SLABC4)       // 8
#define SCOLS   (SLABC4 * 4)           // 256 scalar columns per slab
#define EPS     1e-6f

#define GA      256                    // A-role blocks (reduce)
#define GB      2048                   // B-role blocks (scale)
#define GTOT    (GA + GB)              // 2304 = 256*9, interleaved 8B:1A
#define RPW     (NROWS / (GA * 4))     // 32 rows per A row-worker

// Allocation-free scratch; all state returned to zero each launch sequence.
__device__ float g_u[DCOLS];
__device__ float g_s[DCOLS];
__device__ int   g_cnt[DCOLS];

// ---------------------------------------------------------------------------
// One pipeline stage: A-blocks reduce slab `aslab` (DRAM read, L2-allocate),
// B-blocks scale slab `bslab` (L2-hit reads via ldcs, DRAM writes via stcs).
// Roles interleave 8:1 across blockIdx so both are active in every wave.
__global__ void __launch_bounds__(256)
stage_kernel(const float4* __restrict__ x, float4* __restrict__ y,
             int aslab, int bslab) {
    const int tid = threadIdx.x;
    const unsigned q  = blockIdx.x / 9;
    const unsigned rm = blockIdx.x % 9;

    if (rm == 8) {
        // ================= A role: column sum-of-squares ==================
        if (aslab < 0) return;
        const int aid = (int)q;                   // 0..GA-1
        const int c4l = tid & (SLABC4 - 1);       // 0..63
        const int rw  = tid >> 6;                 // 0..3
        const int w   = aid * 4 + rw;             // 0..1023 row workers
        const size_t coff = (size_t)aslab * SLABC4 + c4l;
        const float4* __restrict__ xp =
            x + (size_t)(w * RPW) * C4TOT + coff; // blocked 32-row stripe

        float ax = 0.f, ay = 0.f, az = 0.f, aw = 0.f;
#pragma unroll 8
        for (int r = 0; r < RPW; ++r) {
            float4 v = xp[(size_t)r * C4TOT];
            ax = fmaf(v.x, v.x, ax); ay = fmaf(v.y, v.y, ay);
            az = fmaf(v.z, v.z, az); aw = fmaf(v.w, v.w, aw);
        }

        // combine 4 row-workers per column in shared (unique slots, no atomics)
        __shared__ float sacc[4][SCOLS];
        sacc[rw][c4l * 4 + 0] = ax;
        sacc[rw][c4l * 4 + 1] = ay;
        sacc[rw][c4l * 4 + 2] = az;
        sacc[rw][c4l * 4 + 3] = aw;
        __syncthreads();

        const int scol = aslab * SCOLS + tid;     // global scalar column
        float v = sacc[0][tid] + sacc[1][tid] + sacc[2][tid] + sacc[3][tid];
        atomicAdd(&g_u[scol], v);
        __threadfence();                          // publish before counting
        if (atomicAdd(&g_cnt[scol], 1) == GA - 1) {
            float tot = atomicExch(&g_u[scol], 0.0f);  // complete sum + reset
            g_s[scol]  = rsqrtf(tot + EPS);
            g_cnt[scol] = 0;                      // reset for next replay
        }
    } else {
        // ================= B role: y = x * s[col] =========================
        if (bslab < 0) return;
        const unsigned bid = q * 8 + rm;          // 0..GB-1
        const unsigned j   = bid * 256 + tid;     // 0..524287 slab-quarter idx
        const int      c4l = j & (SLABC4 - 1);
        const unsigned r0  = j >> 6;              // 0..8191
        const size_t base  = (size_t)r0 * C4TOT + (size_t)bslab * SLABC4 + c4l;
        const size_t step  = (size_t)(NROWS / 4) * C4TOT;   // 8192 rows

        const float4 s = ((const float4*)g_s)[bslab * SLABC4 + c4l];

        float4 v0 = __ldcs(x + base);
        float4 v1 = __ldcs(x + base + step);
        float4 v2 = __ldcs(x + base + 2 * step);
        float4 v3 = __ldcs(x + base + 3 * step);
        v0.x *= s.x; v0.y *= s.y; v0.z *= s.z; v0.w *= s.w;
        v1.x *= s.x; v1.y *= s.y; v1.z *= s.z; v1.w *= s.w;
        v2.x *= s.x; v2.y *= s.y; v2.z *= s.z; v2.w *= s.w;
        v3.x *= s.x; v3.y *= s.y; v3.z *= s.z; v3.w *= s.w;
        __stcs(y + base,            v0);
        __stcs(y + base + step,     v1);
        __stcs(y + base + 2 * step, v2);
        __stcs(y + base + 3 * step, v3);
    }
}

// ---------------------------------------------------------------------------
extern "C" void kernel_launch(void* const* d_in, const int* in_sizes, int n_in,
                              void* d_out, int out_size) {
    const float4* x = (const float4*)d_in[0];
    float4*       y = (float4*)d_out;

    // Software pipeline: stage s reduces slab s while scaling slab s-1.
    for (int s = 0; s <= NSLABS; ++s) {
        int aslab = (s < NSLABS) ? s : -1;
        int bslab = (s > 0) ? s - 1 : -1;
        stage_kernel<<<GTOT, 256>>>(x, y, aslab, bslab);
    }
}